// round 3
// baseline (speedup 1.0000x reference)
#include <cuda_runtime.h>

#define E_ 28
#define H_ 4
#define HD_ 7
#define FF_ 256
#define LMAX_ 8
#define T_ 512
#define B_ 64
#define S_ 4096
#define NSPANS (B_ * T_)

// ---- shared memory layout (floats) ----
#define OFF_WQKV 0          // 84*28 = 2352
#define OFF_BQKV 2352       // 84
#define OFF_WO   2436       // 28*28 = 784
#define OFF_BO   3220       // 28
#define OFF_G1   3248       // 28
#define OFF_B1L  3276       // 28
#define OFF_W1   3304       // 256*28 = 7168
#define OFF_B1   10472      // 256
#define OFF_W2T  10728      // 256*28 = 7168  (TRANSPOSED: row f = 28 contiguous floats)
#define OFF_B2   17896      // 28
#define OFF_G2   17924      // 28
#define OFF_B2L  17952      // 28
#define OFF_PAD  17980      // 28
#define OFF_SCR  18008
#define SCR_PER_WARP 672    // A[224] | Kb[224] | Vb[224]
#define SMEM_FLOATS (OFF_SCR + 8 * SCR_PER_WARP)   // 23384
#define SMEM_BYTES  (SMEM_FLOATS * 4)              // 93536

__device__ __forceinline__ void cp_f4(float* dst, const float* src, int nfloats) {
    const int n4 = nfloats >> 2;
    for (int i = threadIdx.x; i < n4; i += blockDim.x)
        reinterpret_cast<float4*>(dst)[i] = reinterpret_cast<const float4*>(src)[i];
}

// dot of 28-elem register vector x with 28-elem smem row w (float4-vectorized weight loads)
__device__ __forceinline__ float dot28r(const float* x, const float* w) {
    const float4* w4 = reinterpret_cast<const float4*>(w);
    float acc = 0.0f;
#pragma unroll
    for (int j = 0; j < 7; j++) {
        float4 b = w4[j];
        acc = fmaf(x[4 * j + 0], b.x, acc);
        acc = fmaf(x[4 * j + 1], b.y, acc);
        acc = fmaf(x[4 * j + 2], b.z, acc);
        acc = fmaf(x[4 * j + 3], b.w, acc);
    }
    return acc;
}

__global__ __launch_bounds__(256, 2)
void span_transformer_kernel(
    const float* __restrict__ emb,
    const int*   __restrict__ span_lengths,
    const int*   __restrict__ num_spans,
    const float* __restrict__ in_proj_w, const float* __restrict__ in_proj_b,
    const float* __restrict__ out_proj_w, const float* __restrict__ out_proj_b,
    const float* __restrict__ ln1_g, const float* __restrict__ ln1_b,
    const float* __restrict__ lin1_w, const float* __restrict__ lin1_b,
    const float* __restrict__ lin2_w, const float* __restrict__ lin2_b,
    const float* __restrict__ ln2_g, const float* __restrict__ ln2_b,
    const float* __restrict__ pad_token,
    float* __restrict__ outp)
{
    extern __shared__ float sm[];

    // ---- cooperative weight staging ----
    cp_f4(sm + OFF_WQKV, in_proj_w, 2352);
    cp_f4(sm + OFF_BQKV, in_proj_b, 84);
    cp_f4(sm + OFF_WO,   out_proj_w, 784);
    cp_f4(sm + OFF_BO,   out_proj_b, 28);
    cp_f4(sm + OFF_G1,   ln1_g, 28);
    cp_f4(sm + OFF_B1L,  ln1_b, 28);
    cp_f4(sm + OFF_W1,   lin1_w, 7168);
    cp_f4(sm + OFF_B1,   lin1_b, 256);
    // lin2_w is [28][256]; stage TRANSPOSED so column f becomes a contiguous
    // 28-float (112B, 16B-aligned) row.
    for (int i = threadIdx.x; i < 7168; i += blockDim.x) {
        int e = i >> 8;        // source row    (0..27)
        int f = i & 255;       // source column (0..255)
        sm[OFF_W2T + f * 28 + e] = lin2_w[i];
    }
    cp_f4(sm + OFF_B2,   lin2_b, 28);
    cp_f4(sm + OFF_G2,   ln2_g, 28);
    cp_f4(sm + OFF_B2L,  ln2_b, 28);
    cp_f4(sm + OFF_PAD,  pad_token, 28);
    __syncthreads();

    const int warp = threadIdx.x >> 5;
    const int lane = threadIdx.x & 31;
    const int l = lane & 7;      // token within span (layout A)
    const int h = lane >> 3;     // head / E-slice index (layout A)
    const int e0 = h * 7;        // start of this thread's E-slice

    // layout B (FFN): 8 f-groups x 4 token-slots, 2 tokens/thread
    const int fg  = lane & 7;
    const int tk2 = lane >> 3;   // tokens tk2 and tk2+4

    float* A  = sm + OFF_SCR + warp * SCR_PER_WARP;  // x row-major [8][28] (then xn)
    float* Kb = A + 224;                             // k [8][28] (then ao)
    float* Vb = A + 448;                             // v [8][28]

    const int warps_total = gridDim.x * 8;
    for (int span = blockIdx.x * 8 + warp; span < NSPANS; span += warps_total) {
        const int b = span >> 9;
        const int t = span & (T_ - 1);

        // ---- load x: span covers 224 contiguous floats of emb ----
        {
            const float4* src = reinterpret_cast<const float4*>(emb + b * (S_ * E_) + t * 224);
            float4* A4 = reinterpret_cast<float4*>(A);
            A4[lane] = src[lane];
            if (lane < 24) A4[lane + 32] = src[lane + 32];
        }
        __syncwarp();

        // ---- QKV projection (each thread: its head-slice of q,k,v for its token) ----
        float xr[28];
        {
            const float4* r4 = reinterpret_cast<const float4*>(A + l * 28);
#pragma unroll
            for (int j = 0; j < 7; j++) {
                float4 v = r4[j];
                xr[4 * j] = v.x; xr[4 * j + 1] = v.y; xr[4 * j + 2] = v.z; xr[4 * j + 3] = v.w;
            }
        }
        float q[7];
#pragma unroll
        for (int d = 0; d < 7; d++) {
            const int rq = e0 + d;
            q[d]        = sm[OFF_BQKV + rq]      + dot28r(xr, sm + OFF_WQKV + rq * 28);
            float kk    = sm[OFF_BQKV + 28 + rq] + dot28r(xr, sm + OFF_WQKV + (28 + rq) * 28);
            float vv    = sm[OFF_BQKV + 56 + rq] + dot28r(xr, sm + OFF_WQKV + (56 + rq) * 28);
            Kb[l * 28 + rq] = kk;
            Vb[l * 28 + rq] = vv;
        }
        __syncwarp();

        // ---- attention within span (8x8, per head = per thread slice) ----
        const int len = span_lengths[b * T_ + t];
        float s[8];
#pragma unroll
        for (int kk = 0; kk < 8; kk++) {
            const float* kr = Kb + kk * 28 + e0;
            float acc = 0.0f;
#pragma unroll
            for (int d = 0; d < 7; d++) acc = fmaf(q[d], kr[d], acc);
            s[kk] = (kk < len) ? acc * 0.3779644730092272f : -1e9f;
        }
        float mx = s[0];
#pragma unroll
        for (int kk = 1; kk < 8; kk++) mx = fmaxf(mx, s[kk]);
        float p[8], psum = 0.0f;
#pragma unroll
        for (int kk = 0; kk < 8; kk++) { p[kk] = __expf(s[kk] - mx); psum += p[kk]; }
        const float pinv = 1.0f / psum;

        float ao[7];
#pragma unroll
        for (int d = 0; d < 7; d++) {
            float acc = 0.0f;
#pragma unroll
            for (int kk = 0; kk < 8; kk++) acc = fmaf(p[kk], Vb[kk * 28 + e0 + d], acc);
            ao[d] = acc * pinv;
        }
        __syncwarp();   // all score/AV reads of Kb done before overwrite
#pragma unroll
        for (int d = 0; d < 7; d++) Kb[l * 28 + e0 + d] = ao[d];
        __syncwarp();

        // ---- out projection + residual + LN1 ----
        float aor[28];
        {
            const float4* r4 = reinterpret_cast<const float4*>(Kb + l * 28);
#pragma unroll
            for (int j = 0; j < 7; j++) {
                float4 v = r4[j];
                aor[4 * j] = v.x; aor[4 * j + 1] = v.y; aor[4 * j + 2] = v.z; aor[4 * j + 3] = v.w;
            }
        }
        float y[7];
#pragma unroll
        for (int d = 0; d < 7; d++) {
            const int ep = e0 + d;
            float o = sm[OFF_BO + ep] + dot28r(aor, sm + OFF_WO + ep * 28);
            y[d] = A[l * 28 + ep] + o;
        }
        float s1 = 0.0f;
#pragma unroll
        for (int d = 0; d < 7; d++) s1 += y[d];
        s1 += __shfl_xor_sync(0xffffffffu, s1, 8);
        s1 += __shfl_xor_sync(0xffffffffu, s1, 16);
        const float mu1 = s1 * (1.0f / 28.0f);
        float s2 = 0.0f;
#pragma unroll
        for (int d = 0; d < 7; d++) { float dd = y[d] - mu1; s2 += dd * dd; }
        s2 += __shfl_xor_sync(0xffffffffu, s2, 8);
        s2 += __shfl_xor_sync(0xffffffffu, s2, 16);
        const float rs1 = rsqrtf(s2 * (1.0f / 28.0f) + 1e-5f);
#pragma unroll
        for (int d = 0; d < 7; d++) {
            const int ep = e0 + d;
            A[l * 28 + ep] = (y[d] - mu1) * rs1 * sm[OFF_G1 + ep] + sm[OFF_B1L + ep];
        }
        __syncwarp();

        // ==== FFN in layout B: thread (fg, tk2) handles f = 8i+fg for tokens tk2, tk2+4 ====
        // Each W row LDS.128 now has 8 distinct rows across the warp -> 128B/wavefront,
        // and is amortized over 2 tokens.
        float xa[28], xb[28];
        {
            const float4* ra = reinterpret_cast<const float4*>(A + tk2 * 28);
            const float4* rb = reinterpret_cast<const float4*>(A + (tk2 + 4) * 28);
#pragma unroll
            for (int j = 0; j < 7; j++) {
                float4 va = ra[j], vb = rb[j];
                xa[4 * j] = va.x; xa[4 * j + 1] = va.y; xa[4 * j + 2] = va.z; xa[4 * j + 3] = va.w;
                xb[4 * j] = vb.x; xb[4 * j + 1] = vb.y; xb[4 * j + 2] = vb.z; xb[4 * j + 3] = vb.w;
            }
        }
        float ffa[28], ffb[28];
#pragma unroll
        for (int ep = 0; ep < 28; ep++) { ffa[ep] = 0.0f; ffb[ep] = 0.0f; }
#pragma unroll 4
        for (int i = 0; i < 32; i++) {
            const int f = 8 * i + fg;
            const float4* w1r = reinterpret_cast<const float4*>(sm + OFF_W1 + f * 28);
            const float bias = sm[OFF_B1 + f];
            float a1a = bias, a1b = bias;
#pragma unroll
            for (int j = 0; j < 7; j++) {
                float4 w = w1r[j];
                a1a = fmaf(xa[4 * j + 0], w.x, a1a); a1b = fmaf(xb[4 * j + 0], w.x, a1b);
                a1a = fmaf(xa[4 * j + 1], w.y, a1a); a1b = fmaf(xb[4 * j + 1], w.y, a1b);
                a1a = fmaf(xa[4 * j + 2], w.z, a1a); a1b = fmaf(xb[4 * j + 2], w.z, a1b);
                a1a = fmaf(xa[4 * j + 3], w.w, a1a); a1b = fmaf(xb[4 * j + 3], w.w, a1b);
            }
            a1a = fmaxf(a1a, 0.0f);
            a1b = fmaxf(a1b, 0.0f);
            const float4* w2r = reinterpret_cast<const float4*>(sm + OFF_W2T + f * 28);
#pragma unroll
            for (int j = 0; j < 7; j++) {
                float4 w = w2r[j];
                ffa[4 * j + 0] = fmaf(a1a, w.x, ffa[4 * j + 0]); ffb[4 * j + 0] = fmaf(a1b, w.x, ffb[4 * j + 0]);
                ffa[4 * j + 1] = fmaf(a1a, w.y, ffa[4 * j + 1]); ffb[4 * j + 1] = fmaf(a1b, w.y, ffb[4 * j + 1]);
                ffa[4 * j + 2] = fmaf(a1a, w.z, ffa[4 * j + 2]); ffb[4 * j + 2] = fmaf(a1b, w.z, ffb[4 * j + 2]);
                ffa[4 * j + 3] = fmaf(a1a, w.w, ffa[4 * j + 3]); ffb[4 * j + 3] = fmaf(a1b, w.w, ffb[4 * j + 3]);
            }
        }
        // reduce partial ff over the 8 f-groups (xor over lane bits 0..2)
#pragma unroll
        for (int ep = 0; ep < 28; ep++) {
            float va = ffa[ep], vb = ffb[ep];
            va += __shfl_xor_sync(0xffffffffu, va, 1);
            vb += __shfl_xor_sync(0xffffffffu, vb, 1);
            va += __shfl_xor_sync(0xffffffffu, va, 2);
            vb += __shfl_xor_sync(0xffffffffu, vb, 2);
            va += __shfl_xor_sync(0xffffffffu, va, 4);
            vb += __shfl_xor_sync(0xffffffffu, vb, 4);
            const float b2 = sm[OFF_B2 + ep];
            ffa[ep] = va + b2;
            ffb[ep] = vb + b2;
        }

        // ---- residual2 + LN2 for tokens ta=tk2, tb=tk2+4 (redundant across fg) ----
        float mua = 0.0f, mub = 0.0f;
#pragma unroll
        for (int ep = 0; ep < 28; ep++) {
            ffa[ep] += xa[ep]; mua += ffa[ep];
            ffb[ep] += xb[ep]; mub += ffb[ep];
        }
        mua *= (1.0f / 28.0f); mub *= (1.0f / 28.0f);
        float va2 = 0.0f, vb2 = 0.0f;
#pragma unroll
        for (int ep = 0; ep < 28; ep++) {
            float da = ffa[ep] - mua; va2 += da * da;
            float db = ffb[ep] - mub; vb2 += db * db;
        }
        const float rsa = rsqrtf(va2 * (1.0f / 28.0f) + 1e-5f);
        const float rsb = rsqrtf(vb2 * (1.0f / 28.0f) + 1e-5f);

        // ---- masked mean-pool: tokens tk2, tk2+4 in-thread, then reduce over tk2 ----
        const float ma = (tk2 < len)     ? 1.0f : 0.0f;
        const float mb = (tk2 + 4 < len) ? 1.0f : 0.0f;
        float po[28];
#pragma unroll
        for (int ep = 0; ep < 28; ep++) {
            const float g2 = sm[OFF_G2 + ep], b2l = sm[OFF_B2L + ep];
            float x2a = (ffa[ep] - mua) * rsa * g2 + b2l;
            float x2b = (ffb[ep] - mub) * rsb * g2 + b2l;
            po[ep] = x2a * ma + x2b * mb;
        }
#pragma unroll
        for (int ep = 0; ep < 28; ep++) {
            float v = po[ep];
            v += __shfl_xor_sync(0xffffffffu, v, 8);
            v += __shfl_xor_sync(0xffffffffu, v, 16);
            po[ep] = v;
        }
        const float invlen = 1.0f / (float)len;

        // ---- output: pooled (valid) or pad_token ----
        const int ns = num_spans[b];
        float* orow = outp + span * 28;
        __syncwarp();  // FFN reads of A complete before reuse as staging
        if (t < ns) {
            if (lane == 0) {
                float4* A4 = reinterpret_cast<float4*>(A);
#pragma unroll
                for (int j = 0; j < 7; j++) {
                    float4 v;
                    v.x = po[4 * j] * invlen;
                    v.y = po[4 * j + 1] * invlen;
                    v.z = po[4 * j + 2] * invlen;
                    v.w = po[4 * j + 3] * invlen;
                    A4[j] = v;
                }
            }
            __syncwarp();
            if (lane < 7)
                reinterpret_cast<float4*>(orow)[lane] = reinterpret_cast<float4*>(A)[lane];
        } else {
            if (lane < 7)
                reinterpret_cast<float4*>(orow)[lane] =
                    reinterpret_cast<const float4*>(sm + OFF_PAD)[lane];
        }
        __syncwarp();   // A reused next iteration
    }
}

extern "C" void kernel_launch(void* const* d_in, const int* in_sizes, int n_in,
                              void* d_out, int out_size) {
    const float* emb          = (const float*)d_in[0];
    const int*   span_lengths = (const int*)  d_in[1];
    const int*   num_spans    = (const int*)  d_in[2];
    const float* in_proj_w    = (const float*)d_in[3];
    const float* in_proj_b    = (const float*)d_in[4];
    const float* out_proj_w   = (const float*)d_in[5];
    const float* out_proj_b   = (const float*)d_in[6];
    const float* ln1_g        = (const float*)d_in[7];
    const float* ln1_b        = (const float*)d_in[8];
    const float* lin1_w       = (const float*)d_in[9];
    const float* lin1_b       = (const float*)d_in[10];
    const float* lin2_w       = (const float*)d_in[11];
    const float* lin2_b       = (const float*)d_in[12];
    const float* ln2_g        = (const float*)d_in[13];
    const float* ln2_b        = (const float*)d_in[14];
    const float* pad_token    = (const float*)d_in[15];
    float* outp = (float*)d_out;

    cudaFuncSetAttribute(span_transformer_kernel,
                         cudaFuncAttributeMaxDynamicSharedMemorySize, SMEM_BYTES);

    span_transformer_kernel<<<296, 256, SMEM_BYTES>>>(
        emb, span_lengths, num_spans,
        in_proj_w, in_proj_b, out_proj_w, out_proj_b,
        ln1_g, ln1_b, lin1_w, lin1_b, lin2_w, lin2_b,
        ln2_g, ln2_b, pad_token, outp);
}